// round 15
// baseline (speedup 1.0000x reference)
#include <cuda_runtime.h>
#include <cuda_fp16.h>
#include <math.h>

#define N_NODES   100000
#define N_EDGES   1250000
#define HID       64
#define N_RBF     32
#define N_GRAPHS  512
#define N_EXPERTS 8
#define N_LAYERS  3
#define MAX_Z     100
#define GATE_IN   72
#define G1        64
#define G2        32
#define TABLE     4096
#define CUTOFF    6.0f
#define PH        72      // smem half pitch (halves)
#define SCAN_BLK  1024
#define SCAN_NB   ((N_NODES + SCAN_BLK - 1) / SCAN_BLK)  // 98

// ---------------- scratch (no allocations allowed) ----------------
__device__ __align__(256) float  g_x[N_NODES * HID];
__device__ __align__(256) __half g_yh[N_NODES * HID];
__device__ __align__(256) float  g_agg[N_NODES * HID];   // unused now (layout kept)
__device__ __align__(256) float  g_tabf[N_LAYERS][(TABLE + 1) * HID];
// packed half table: per row i (256B): 32 x { val half2, delta half2 }
__device__ __align__(256) __half g_tabh[N_LAYERS][TABLE * 128];
__device__ __align__(256) float  g_pooled[N_GRAPHS * HID];
__device__ float g_counts[N_GRAPHS];
// dst-sorted CSR
__device__ __align__(256) int   g_hist[N_NODES];
__device__ __align__(256) int   g_rowptr[N_NODES + 1];
__device__ __align__(256) int   g_cursor[N_NODES];
__device__ __align__(256) uint2 g_col[N_EDGES];   // .x = src | (i0<<17), .y = bits(fr)
__device__ int g_bsum[SCAN_NB];
// ping-pong partner for y (appended; existing layout untouched)
__device__ __align__(256) __half g_yh2[N_NODES * HID];

__device__ __forceinline__ float silu_f(float v) { return v / (1.0f + __expf(-v)); }

// ---------------- mma / ldmatrix helpers --------------------------
__device__ __forceinline__ unsigned smem_u32(const void* p) {
    return (unsigned)__cvta_generic_to_shared(p);
}
__device__ __forceinline__ void ldmx4(unsigned addr, unsigned& r0, unsigned& r1,
                                      unsigned& r2, unsigned& r3) {
    asm volatile("ldmatrix.sync.aligned.m8n8.x4.shared.b16 {%0,%1,%2,%3}, [%4];"
                 : "=r"(r0), "=r"(r1), "=r"(r2), "=r"(r3) : "r"(addr));
}
__device__ __forceinline__ void mma16816(float d[4], const unsigned a[4], const unsigned* b) {
    asm volatile(
        "mma.sync.aligned.m16n8k16.row.col.f32.f16.f16.f32 "
        "{%0,%1,%2,%3}, {%4,%5,%6,%7}, {%8,%9}, {%0,%1,%2,%3};"
        : "+f"(d[0]), "+f"(d[1]), "+f"(d[2]), "+f"(d[3])
        : "r"(a[0]), "r"(a[1]), "r"(a[2]), "r"(a[3]), "r"(b[0]), "r"(b[1]));
}
__device__ __forceinline__ unsigned packh2(float a, float b) {
    __half2 h = __floats2half2_rn(a, b);
    return *(unsigned*)&h;
}

// Stage W (torch [out,in] = [c][k], fp32) -> Wh[c][k] fp16. 128 threads.
__device__ __forceinline__ void stage_w(const float* __restrict__ W, __half (*Wh)[PH], int tid) {
#pragma unroll
    for (int it = 0; it < 8; it++) {
        int idx = it * 128 + tid;
        int kq = idx & 15;
        int c = idx >> 4;
        float4 v = *(const float4*)&W[c * HID + kq * 4];
        unsigned h0 = packh2(v.x, v.y), h1 = packh2(v.z, v.w);
        *(uint2*)&Wh[c][kq * 4] = make_uint2(h0, h1);
    }
}

// Same, 256 threads.
__device__ __forceinline__ void stage_w256(const float* __restrict__ W, __half (*Wh)[PH], int tid) {
#pragma unroll
    for (int it = 0; it < 4; it++) {
        int idx = it * 256 + tid;
        int kq = idx & 15;
        int c = idx >> 4;
        float4 v = *(const float4*)&W[c * HID + kq * 4];
        unsigned h0 = packh2(v.x, v.y), h1 = packh2(v.z, v.w);
        *(uint2*)&Wh[c][kq * 4] = make_uint2(h0, h1);
    }
}

// Full 16x64x64 warp GEMM: D = Ah(rows 16w..16w+15) @ Wh^T.
__device__ __forceinline__ void warp_gemm_smemA(const __half (*Ah)[PH], const __half (*Wh)[PH],
                                                int w, int lane, float D[8][4]) {
    int r = lane & 7, m = lane >> 3;
    unsigned a[4][4];
#pragma unroll
    for (int kc = 0; kc < 4; kc++)
        ldmx4(smem_u32(&Ah[w * 16 + r + (m & 1) * 8][kc * 16 + (m >> 1) * 8]),
              a[kc][0], a[kc][1], a[kc][2], a[kc][3]);
#pragma unroll
    for (int i = 0; i < 8; i++)
#pragma unroll
        for (int j = 0; j < 4; j++) D[i][j] = 0.0f;
#pragma unroll
    for (int kc = 0; kc < 4; kc++)
#pragma unroll
        for (int nt2 = 0; nt2 < 4; nt2++) {
            unsigned b[4];
            ldmx4(smem_u32(&Wh[nt2 * 16 + r + (m >> 1) * 8][kc * 16 + (m & 1) * 8]),
                  b[0], b[1], b[2], b[3]);
            mma16816(D[2 * nt2], a[kc], b);
            mma16816(D[2 * nt2 + 1], a[kc], b + 2);
        }
}

// Same, but A fragments already in registers.
__device__ __forceinline__ void warp_gemm_regA(const unsigned a[4][4], const __half (*Wh)[PH],
                                               int lane, float D[8][4]) {
    int r = lane & 7, m = lane >> 3;
#pragma unroll
    for (int i = 0; i < 8; i++)
#pragma unroll
        for (int j = 0; j < 4; j++) D[i][j] = 0.0f;
#pragma unroll
    for (int kc = 0; kc < 4; kc++)
#pragma unroll
        for (int nt2 = 0; nt2 < 4; nt2++) {
            unsigned b[4];
            ldmx4(smem_u32(&Wh[nt2 * 16 + r + (m >> 1) * 8][kc * 16 + (m & 1) * 8]),
                  b[0], b[1], b[2], b[3]);
            mma16816(D[2 * nt2], a[kc], b);
            mma16816(D[2 * nt2 + 1], a[kc], b + 2);
        }
}

// pack D (8 ntiles) -> next-GEMM A fragments
__device__ __forceinline__ void pack_a(const float D[8][4], unsigned a[4][4]) {
#pragma unroll
    for (int kc = 0; kc < 4; kc++) {
        a[kc][0] = packh2(D[2 * kc][0], D[2 * kc][1]);
        a[kc][1] = packh2(D[2 * kc][2], D[2 * kc][3]);
        a[kc][2] = packh2(D[2 * kc + 1][0], D[2 * kc + 1][1]);
        a[kc][3] = packh2(D[2 * kc + 1][2], D[2 * kc + 1][3]);
    }
}

// ---------------- filter-network lookup table (fp32 values) -------
__global__ void k_tables(const float* __restrict__ fW1, const float* __restrict__ fb1,
                         const float* __restrict__ fW2, const float* __restrict__ fb2) {
    int l = blockIdx.y;
    int i = blockIdx.x;
    int c = threadIdx.x;
    __shared__ float rbf[N_RBF];
    __shared__ float h[HID];

    float w = CUTOFF * (float)i / (float)TABLE;
    if (c < N_RBF) {
        float delta = CUTOFF / (float)(N_RBF - 1);
        float off = delta * (float)c;
        float coeff = -0.5f / (delta * delta);
        float d = w - off;
        rbf[c] = expf(coeff * d * d);
    }
    __syncthreads();

    const float* W1 = fW1 + (l * HID + c) * N_RBF;
    float acc = fb1[l * HID + c];
#pragma unroll
    for (int k = 0; k < N_RBF; k++) acc += rbf[k] * W1[k];
    h[c] = acc / (1.0f + expf(-acc));
    __syncthreads();

    const float* W2 = fW2 + (l * HID + c) * HID;
    float acc2 = fb2[l * HID + c];
#pragma unroll
    for (int k = 0; k < HID; k++) acc2 += h[k] * W2[k];
    g_tabf[l][i * HID + c] = acc2;
}

__global__ void k_tabpack() {
    int idx = blockIdx.x * blockDim.x + threadIdx.x;
    if (idx >= N_LAYERS * TABLE * 32) return;
    int j = idx & 31;
    int i = (idx >> 5) % TABLE;
    int l = idx / (TABLE * 32);
    float2 v = *(const float2*)&g_tabf[l][i * HID + j * 2];
    float2 vn = *(const float2*)&g_tabf[l][(i + 1) * HID + j * 2];
    uint2 o;
    o.x = packh2(v.x, v.y);
    o.y = packh2(vn.x - v.x, vn.y - v.y);
    *(uint2*)&g_tabh[l][i * 128 + j * 4] = o;
}

// ---------------- per-launch zeroing ------------------------------
__global__ void k_zero() {
    int idx = blockIdx.x * blockDim.x + threadIdx.x;
    if (idx < N_NODES) g_hist[idx] = 0;
    if (idx < N_GRAPHS * HID) g_pooled[idx] = 0.0f;
    if (idx < N_GRAPHS) g_counts[idx] = 0.0f;
}

// ---------------- CSR build ---------------------------------------
__global__ void k_hist(const int* __restrict__ edge_index) {
    int e = blockIdx.x * blockDim.x + threadIdx.x;
    if (e >= N_EDGES) return;
    atomicAdd(&g_hist[edge_index[N_EDGES + e]], 1);
}

__global__ void k_scan_a() {
    __shared__ int ws[8];
    int b = blockIdx.x, t = threadIdx.x;
    int base = b * SCAN_BLK + t * 4;
    int s = 0;
#pragma unroll
    for (int i = 0; i < 4; i++) {
        int idx = base + i;
        if (idx < N_NODES) s += g_hist[idx];
    }
#pragma unroll
    for (int o = 16; o; o >>= 1) s += __shfl_down_sync(~0u, s, o);
    if ((t & 31) == 0) ws[t >> 5] = s;
    __syncthreads();
    if (t == 0) {
        int v = 0;
        for (int i = 0; i < 8; i++) v += ws[i];
        g_bsum[b] = v;
    }
}

__global__ void k_scan_b() {
    __shared__ int sm[SCAN_NB];
    int t = threadIdx.x;
    if (t < SCAN_NB) sm[t] = g_bsum[t];
    __syncthreads();
    if (t == 0) {
        int run = 0;
        for (int i = 0; i < SCAN_NB; i++) {
            int v = sm[i];
            sm[i] = run;
            run += v;
        }
    }
    __syncthreads();
    if (t < SCAN_NB) g_bsum[t] = sm[t];
}

__global__ void k_scan_c() {
    __shared__ int wsum[8];
    int b = blockIdx.x, t = threadIdx.x, lane = t & 31, wid = t >> 5;
    int base = b * SCAN_BLK + t * 4;
    int v[4];
    int s = 0;
#pragma unroll
    for (int i = 0; i < 4; i++) {
        int idx = base + i;
        v[i] = (idx < N_NODES) ? g_hist[idx] : 0;
        s += v[i];
    }
    int sc = s;
#pragma unroll
    for (int o = 1; o < 32; o <<= 1) {
        int u = __shfl_up_sync(~0u, sc, o);
        if (lane >= o) sc += u;
    }
    if (lane == 31) wsum[wid] = sc;
    __syncthreads();
    if (t == 0) {
        int run = 0;
        for (int i = 0; i < 8; i++) {
            int u = wsum[i];
            wsum[i] = run;
            run += u;
        }
    }
    __syncthreads();
    int off = g_bsum[b] + wsum[wid] + sc - s;
#pragma unroll
    for (int i = 0; i < 4; i++) {
        int idx = base + i;
        if (idx < N_NODES) {
            g_rowptr[idx] = off;
            g_cursor[idx] = off;
            off += v[i];
        }
    }
    if (b == 0 && t == 0) g_rowptr[N_NODES] = N_EDGES;
}

__global__ void k_scatter(const int* __restrict__ edge_index, const float* __restrict__ ew) {
    int e = blockIdx.x * blockDim.x + threadIdx.x;
    if (e >= N_EDGES) return;
    int src = edge_index[e];
    int dst = edge_index[N_EDGES + e];
    float w = __ldg(&ew[e]);
    float tt = w * ((float)TABLE / CUTOFF);
    int i0 = (int)tt;
    if (i0 < 0) i0 = 0;
    if (i0 > TABLE - 1) i0 = TABLE - 1;
    float fr = tt - (float)i0;
    int pos = atomicAdd(&g_cursor[dst], 1);
    g_col[pos] = make_uint2((unsigned)src | ((unsigned)i0 << 17), __float_as_uint(fr));
}

// ---------------- layer 0: x = emb[z]; y = x @ dW[0].T + db[0] ----
__global__ __launch_bounds__(128) void k_embed_ylinear(const int* __restrict__ z,
                                                       const float* __restrict__ emb,
                                                       const float* __restrict__ dW0,
                                                       const float* __restrict__ db0) {
    __shared__ __align__(16) __half Ah[64][PH];
    __shared__ __align__(16) __half Wh[64][PH];
    int tid = threadIdx.x;
    int node0 = blockIdx.x * 64;
    stage_w(dW0, Wh, tid);
#pragma unroll
    for (int it = 0; it < 8; it++) {
        int idx = it * 128 + tid;
        int q = idx & 15;
        int n = idx >> 4;
        uint2 o = make_uint2(0u, 0u);
        if (node0 + n < N_NODES) {
            int zz = __ldg(&z[node0 + n]);
            float4 v = *(const float4*)&emb[zz * HID + q * 4];
            *(float4*)&g_x[(size_t)(node0 + n) * HID + q * 4] = v;
            o = make_uint2(packh2(v.x, v.y), packh2(v.z, v.w));
        }
        *(uint2*)&Ah[n][q * 4] = o;
    }
    __syncthreads();

    int w = tid >> 5, lane = tid & 31;
    float D[8][4];
    warp_gemm_smemA(Ah, Wh, w, lane, D);

    int qr = lane >> 2, qc = (lane & 3) * 2;
    int row0 = node0 + w * 16 + qr, row1 = row0 + 8;
#pragma unroll
    for (int nt = 0; nt < 8; nt++) {
        int c0 = nt * 8 + qc;
        float bx = __ldg(&db0[c0]), by = __ldg(&db0[c0 + 1]);
        if (row0 < N_NODES)
            *(__half2*)&g_yh[(size_t)row0 * HID + c0] = __floats2half2_rn(D[nt][0] + bx, D[nt][1] + by);
        if (row1 < N_NODES)
            *(__half2*)&g_yh[(size_t)row1 * HID + c0] = __floats2half2_rn(D[nt][2] + bx, D[nt][3] + by);
    }
}

// -------- FUSED layer kernel: aggregation -> smem A-tile -> 3-GEMM chain
// 256 threads. Phase 1: 8 warps x 8 nodes aggregate (reads ysrc), writing
// fp16 results straight into the smem A tile (g_agg eliminated).
// Phase 2: warps 0-3 run the update GEMM chain; next-layer y -> ydst.
template <bool LAST>
__global__ __launch_bounds__(256) void k_fused(const float* __restrict__ uW1,
                                               const float* __restrict__ ub1,
                                               const float* __restrict__ uW2,
                                               const float* __restrict__ ub2,
                                               const float* __restrict__ dWn,
                                               const float* __restrict__ dbn,
                                               int layer, int ysel) {
    __shared__ __align__(16) __half Ah[64][PH];
    __shared__ __align__(16) __half W1h[64][PH];
    __shared__ __align__(16) __half W2h[64][PH];
    __shared__ __align__(16) __half Wnh[64][PH];
    int tid = threadIdx.x;
    int w = tid >> 5, lane = tid & 31;
    int node0 = blockIdx.x * 64;

    const __half* __restrict__ ysrc = ysel ? g_yh2 : g_yh;
    __half* __restrict__ ydst = ysel ? g_yh : g_yh2;

    stage_w256(uW1 + layer * HID * HID, W1h, tid);
    stage_w256(uW2 + layer * HID * HID, W2h, tid);
    if (!LAST) stage_w256(dWn, Wnh, tid);

    // ---- Phase 1: aggregation. warp w handles nodes node0 + w*8 .. +7
    const __half* tab = g_tabh[layer];
#pragma unroll 1
    for (int i = 0; i < 8; i++) {
        int nloc = w * 8 + i;
        int node = node0 + nloc;
        float2 acc = make_float2(0.0f, 0.0f);
        if (node < N_NODES) {
            int beg = g_rowptr[node];
            int end = g_rowptr[node + 1];
            for (int p = beg; p < end; p++) {
                uint2 rec = __ldg(&g_col[p]);
                int src = (int)(rec.x & 0x1FFFFu);
                int i0 = (int)(rec.x >> 17);
                float fr = __uint_as_float(rec.y);
                __half2 yh = *(const __half2*)&ysrc[(size_t)src * HID + lane * 2];
                uint2 tv = __ldg((const uint2*)&tab[(size_t)i0 * 128 + lane * 4]);
                float2 y2 = __half22float2(yh);
                float2 v2 = __half22float2(*(__half2*)&tv.x);
                float2 d2 = __half22float2(*(__half2*)&tv.y);
                acc.x = fmaf(y2.x, fmaf(fr, d2.x, v2.x), acc.x);
                acc.y = fmaf(y2.y, fmaf(fr, d2.y, v2.y), acc.y);
            }
        }
        *(__half2*)&Ah[nloc][lane * 2] = __floats2half2_rn(acc.x, acc.y);
    }
    __syncthreads();   // the ONLY barrier

    // ---- Phase 2: GEMM chain on warps 0-3
    if (w >= 4) return;
    int qr = lane >> 2, qc = (lane & 3) * 2;
    int row0 = node0 + w * 16 + qr, row1 = row0 + 8;

    float D[8][4];
    warp_gemm_smemA(Ah, W1h, w, lane, D);

#pragma unroll
    for (int nt = 0; nt < 8; nt++) {
        int c0 = nt * 8 + qc;
        float bx = __ldg(&ub1[layer * HID + c0]), by = __ldg(&ub1[layer * HID + c0 + 1]);
        D[nt][0] = silu_f(D[nt][0] + bx);
        D[nt][1] = silu_f(D[nt][1] + by);
        D[nt][2] = silu_f(D[nt][2] + bx);
        D[nt][3] = silu_f(D[nt][3] + by);
    }
    unsigned a[4][4];
    pack_a(D, a);

    warp_gemm_regA(a, W2h, lane, D);

#pragma unroll
    for (int nt = 0; nt < 8; nt++) {
        int c0 = nt * 8 + qc;
        float bx = __ldg(&ub2[layer * HID + c0]), by = __ldg(&ub2[layer * HID + c0 + 1]);
        if (row0 < N_NODES) {
            float2 xv = *(const float2*)&g_x[(size_t)row0 * HID + c0];
            D[nt][0] += bx + xv.x;
            D[nt][1] += by + xv.y;
            *(float2*)&g_x[(size_t)row0 * HID + c0] = make_float2(D[nt][0], D[nt][1]);
        }
        if (row1 < N_NODES) {
            float2 xv = *(const float2*)&g_x[(size_t)row1 * HID + c0];
            D[nt][2] += bx + xv.x;
            D[nt][3] += by + xv.y;
            *(float2*)&g_x[(size_t)row1 * HID + c0] = make_float2(D[nt][2], D[nt][3]);
        }
    }

    if (!LAST) {
        pack_a(D, a);
        warp_gemm_regA(a, Wnh, lane, D);
#pragma unroll
        for (int nt = 0; nt < 8; nt++) {
            int c0 = nt * 8 + qc;
            float bx = __ldg(&dbn[c0]), by = __ldg(&dbn[c0 + 1]);
            if (row0 < N_NODES)
                *(__half2*)&ydst[(size_t)row0 * HID + c0] =
                    __floats2half2_rn(D[nt][0] + bx, D[nt][1] + by);
            if (row1 < N_NODES)
                *(__half2*)&ydst[(size_t)row1 * HID + c0] =
                    __floats2half2_rn(D[nt][2] + bx, D[nt][3] + by);
        }
    }
}

// ---------------- mean pool (batch sorted: segmented flush) -------
__global__ void k_pool(const int* __restrict__ batch) {
    int tid = threadIdx.x;
    int c = tid & 63;
    int grp = tid >> 6;
    long base = (long)blockIdx.x * 64 + grp * 16;
    if (base >= N_NODES) return;

    float acc = 0.0f;
    int cur = -1;
    for (int i = 0; i < 16; i++) {
        long n = base + i;
        if (n >= N_NODES) break;
        int g = __ldg(&batch[n]);
        if (g != cur) {
            if (cur >= 0) atomicAdd(&g_pooled[cur * HID + c], acc);
            cur = g;
            acc = 0.0f;
        }
        acc += g_x[n * HID + c];
    }
    if (cur >= 0) atomicAdd(&g_pooled[cur * HID + c], acc);

    if (c == 0) {
        float cnt = 0.0f;
        int cg2 = -1;
        for (int i = 0; i < 16; i++) {
            long n = base + i;
            if (n >= N_NODES) break;
            int g = __ldg(&batch[n]);
            if (g != cg2) {
                if (cg2 >= 0) atomicAdd(&g_counts[cg2], cnt);
                cg2 = g;
                cnt = 0.0f;
            }
            cnt += 1.0f;
        }
        if (cg2 >= 0) atomicAdd(&g_counts[cg2], cnt);
    }
}

// ---------------- gate MLP + softmax + prediction -----------------
__global__ void k_gate(const float* __restrict__ mlip,
                       const float* __restrict__ gW1, const float* __restrict__ gb1,
                       const float* __restrict__ gW2, const float* __restrict__ gb2,
                       const float* __restrict__ gW3, const float* __restrict__ gb3,
                       float* __restrict__ out) {
    int g = blockIdx.x;
    int c = threadIdx.x;
    __shared__ float in[GATE_IN];
    __shared__ float h1[G1];
    __shared__ float h2[G2];
    __shared__ float lg[N_EXPERTS];

    float cnt = fmaxf(g_counts[g], 1.0f);
    in[c] = g_pooled[g * HID + c] / cnt;
    if (c < N_EXPERTS) in[HID + c] = mlip[g * N_EXPERTS + c];
    __syncthreads();

    float acc = gb1[c];
#pragma unroll
    for (int k = 0; k < GATE_IN; k++) acc += in[k] * gW1[c * GATE_IN + k];
    h1[c] = fmaxf(acc, 0.0f);
    __syncthreads();

    if (c < G2) {
        float a2 = gb2[c];
#pragma unroll
        for (int k = 0; k < G1; k++) a2 += h1[k] * gW2[c * G1 + k];
        h2[c] = fmaxf(a2, 0.0f);
    }
    __syncthreads();

    if (c < N_EXPERTS) {
        float a3 = gb3[c];
#pragma unroll
        for (int k = 0; k < G2; k++) a3 += h2[k] * gW3[c * G2 + k];
        lg[c] = a3;
        out[g * N_EXPERTS + c] = a3;
    }
    __syncthreads();

    if (c == 0) {
        float m = lg[0];
        for (int k = 1; k < N_EXPERTS; k++) m = fmaxf(m, lg[k]);
        float wts[N_EXPERTS];
        float ssum = 0.0f;
        for (int k = 0; k < N_EXPERTS; k++) {
            wts[k] = expf(lg[k] - m);
            ssum += wts[k];
        }
        float pred = 0.0f;
        for (int k = 0; k < N_EXPERTS; k++) {
            float wv = wts[k] / ssum;
            out[N_GRAPHS * N_EXPERTS + g * N_EXPERTS + k] = wv;
            pred += mlip[g * N_EXPERTS + k] * wv;
        }
        out[2 * N_GRAPHS * N_EXPERTS + g] = pred;
    }
}

// ---------------- launch ------------------------------------------
extern "C" void kernel_launch(void* const* d_in, const int* in_sizes, int n_in,
                              void* d_out, int out_size) {
    const int* z = (const int*)d_in[0];
    const int* edge_index = (const int*)d_in[1];
    const float* ew = (const float*)d_in[2];
    const int* batch = (const int*)d_in[3];
    const float* mlip = (const float*)d_in[4];
    const float* emb = (const float*)d_in[5];
    const float* fW1 = (const float*)d_in[6];
    const float* fb1 = (const float*)d_in[7];
    const float* fW2 = (const float*)d_in[8];
    const float* fb2 = (const float*)d_in[9];
    const float* dW = (const float*)d_in[10];
    const float* db = (const float*)d_in[11];
    const float* uW1 = (const float*)d_in[12];
    const float* ub1 = (const float*)d_in[13];
    const float* uW2 = (const float*)d_in[14];
    const float* ub2 = (const float*)d_in[15];
    const float* gW1 = (const float*)d_in[16];
    const float* gb1 = (const float*)d_in[17];
    const float* gW2 = (const float*)d_in[18];
    const float* gb2 = (const float*)d_in[19];
    const float* gW3 = (const float*)d_in[20];
    const float* gb3 = (const float*)d_in[21];
    float* out = (float*)d_out;

    k_zero<<<(N_NODES + 255) / 256, 256>>>();
    k_hist<<<(N_EDGES + 255) / 256, 256>>>(edge_index);
    k_scan_a<<<SCAN_NB, 256>>>();
    k_scan_b<<<1, 128>>>();
    k_scan_c<<<SCAN_NB, 256>>>();
    k_scatter<<<(N_EDGES + 255) / 256, 256>>>(edge_index, ew);
    {
        dim3 grid(TABLE + 1, N_LAYERS);
        k_tables<<<grid, HID>>>(fW1, fb1, fW2, fb2);
        int total = N_LAYERS * TABLE * 32;
        k_tabpack<<<(total + 255) / 256, 256>>>();
    }

    int node_blocks = (N_NODES + 63) / 64;  // 1563

    k_embed_ylinear<<<node_blocks, 128>>>(z, emb, dW, db);

    // layer 0: read g_yh, write g_yh2
    k_fused<false><<<node_blocks, 256>>>(uW1, ub1, uW2, ub2,
                                         dW + 1 * HID * HID, db + 1 * HID, 0, 0);
    // layer 1: read g_yh2, write g_yh
    k_fused<false><<<node_blocks, 256>>>(uW1, ub1, uW2, ub2,
                                         dW + 2 * HID * HID, db + 2 * HID, 1, 1);
    // layer 2: read g_yh, no y write
    k_fused<true><<<node_blocks, 256>>>(uW1, ub1, uW2, ub2,
                                        (const float*)0, (const float*)0, 2, 0);

    k_pool<<<node_blocks, 256>>>(batch);
    k_gate<<<N_GRAPHS, HID>>>(mlip, gW1, gb1, gW2, gb2, gW3, gb3, out);
}

// round 16
// speedup vs baseline: 1.0611x; 1.0611x over previous
#include <cuda_runtime.h>
#include <cuda_fp16.h>
#include <math.h>

#define N_NODES   100000
#define N_EDGES   1250000
#define HID       64
#define N_RBF     32
#define N_GRAPHS  512
#define N_EXPERTS 8
#define N_LAYERS  3
#define MAX_Z     100
#define GATE_IN   72
#define G1        64
#define G2        32
#define TABLE     4096
#define CUTOFF    6.0f
#define PH        72      // smem half pitch (halves)
#define SCAN_BLK  1024
#define SCAN_NB   ((N_NODES + SCAN_BLK - 1) / SCAN_BLK)  // 98

// ---------------- scratch (no allocations allowed) ----------------
__device__ __align__(256) float  g_x[N_NODES * HID];
__device__ __align__(256) __half g_yh[N_NODES * HID];
__device__ __align__(256) float  g_agg[N_NODES * HID];   // retired (layout kept)
__device__ __align__(256) float  g_tabf[N_LAYERS][(TABLE + 1) * HID];
// packed half table: per row i (256B): 32 x { val half2, delta half2 }
__device__ __align__(256) __half g_tabh[N_LAYERS][TABLE * 128];
__device__ __align__(256) float  g_pooled[N_GRAPHS * HID];
__device__ float g_counts[N_GRAPHS];
// dst-sorted CSR
__device__ __align__(256) int   g_hist[N_NODES];
__device__ __align__(256) int   g_rowptr[N_NODES + 1];
__device__ __align__(256) int   g_cursor[N_NODES];
__device__ __align__(256) uint2 g_col[N_EDGES];   // .x = src | (i0<<17), .y = bits(fr)
__device__ int g_bsum[SCAN_NB];
// appended: fp16 aggregation buffer (halves g_agg traffic)
__device__ __align__(256) __half g_aggh[N_NODES * HID];

__device__ __forceinline__ float silu_f(float v) { return v / (1.0f + __expf(-v)); }

// ---------------- mma / ldmatrix helpers --------------------------
__device__ __forceinline__ unsigned smem_u32(const void* p) {
    return (unsigned)__cvta_generic_to_shared(p);
}
__device__ __forceinline__ void ldmx4(unsigned addr, unsigned& r0, unsigned& r1,
                                      unsigned& r2, unsigned& r3) {
    asm volatile("ldmatrix.sync.aligned.m8n8.x4.shared.b16 {%0,%1,%2,%3}, [%4];"
                 : "=r"(r0), "=r"(r1), "=r"(r2), "=r"(r3) : "r"(addr));
}
__device__ __forceinline__ void mma16816(float d[4], const unsigned a[4], const unsigned* b) {
    asm volatile(
        "mma.sync.aligned.m16n8k16.row.col.f32.f16.f16.f32 "
        "{%0,%1,%2,%3}, {%4,%5,%6,%7}, {%8,%9}, {%0,%1,%2,%3};"
        : "+f"(d[0]), "+f"(d[1]), "+f"(d[2]), "+f"(d[3])
        : "r"(a[0]), "r"(a[1]), "r"(a[2]), "r"(a[3]), "r"(b[0]), "r"(b[1]));
}
__device__ __forceinline__ unsigned packh2(float a, float b) {
    __half2 h = __floats2half2_rn(a, b);
    return *(unsigned*)&h;
}

// Stage W (torch [out,in] = [c][k], fp32) -> Wh[c][k] fp16. 128 threads.
__device__ __forceinline__ void stage_w(const float* __restrict__ W, __half (*Wh)[PH], int tid) {
#pragma unroll
    for (int it = 0; it < 8; it++) {
        int idx = it * 128 + tid;
        int kq = idx & 15;
        int c = idx >> 4;
        float4 v = *(const float4*)&W[c * HID + kq * 4];
        unsigned h0 = packh2(v.x, v.y), h1 = packh2(v.z, v.w);
        *(uint2*)&Wh[c][kq * 4] = make_uint2(h0, h1);
    }
}

// Stage fp16 node tile -> Ah[n][k] (plain copy; zero-fill invalid rows). 128 threads.
__device__ __forceinline__ void stage_ah(const __half* __restrict__ src, int node0,
                                         __half (*Ah)[PH], int tid) {
#pragma unroll
    for (int it = 0; it < 4; it++) {
        int idx = it * 128 + tid;   // 0..511
        int q = idx & 7;            // 8 halves per chunk
        int n = idx >> 3;           // 0..63
        uint4 o = make_uint4(0u, 0u, 0u, 0u);
        if (node0 + n < N_NODES)
            o = *(const uint4*)&src[(size_t)(node0 + n) * HID + q * 8];
        *(uint4*)&Ah[n][q * 8] = o;
    }
}

// Full 16x64x64 warp GEMM: D = Ah(rows 16w..16w+15) @ Wh^T.
__device__ __forceinline__ void warp_gemm_smemA(const __half (*Ah)[PH], const __half (*Wh)[PH],
                                                int w, int lane, float D[8][4]) {
    int r = lane & 7, m = lane >> 3;
    unsigned a[4][4];
#pragma unroll
    for (int kc = 0; kc < 4; kc++)
        ldmx4(smem_u32(&Ah[w * 16 + r + (m & 1) * 8][kc * 16 + (m >> 1) * 8]),
              a[kc][0], a[kc][1], a[kc][2], a[kc][3]);
#pragma unroll
    for (int i = 0; i < 8; i++)
#pragma unroll
        for (int j = 0; j < 4; j++) D[i][j] = 0.0f;
#pragma unroll
    for (int kc = 0; kc < 4; kc++)
#pragma unroll
        for (int nt2 = 0; nt2 < 4; nt2++) {
            unsigned b[4];
            ldmx4(smem_u32(&Wh[nt2 * 16 + r + (m >> 1) * 8][kc * 16 + (m & 1) * 8]),
                  b[0], b[1], b[2], b[3]);
            mma16816(D[2 * nt2], a[kc], b);
            mma16816(D[2 * nt2 + 1], a[kc], b + 2);
        }
}

// Same, but A fragments already in registers.
__device__ __forceinline__ void warp_gemm_regA(const unsigned a[4][4], const __half (*Wh)[PH],
                                               int lane, float D[8][4]) {
    int r = lane & 7, m = lane >> 3;
#pragma unroll
    for (int i = 0; i < 8; i++)
#pragma unroll
        for (int j = 0; j < 4; j++) D[i][j] = 0.0f;
#pragma unroll
    for (int kc = 0; kc < 4; kc++)
#pragma unroll
        for (int nt2 = 0; nt2 < 4; nt2++) {
            unsigned b[4];
            ldmx4(smem_u32(&Wh[nt2 * 16 + r + (m >> 1) * 8][kc * 16 + (m & 1) * 8]),
                  b[0], b[1], b[2], b[3]);
            mma16816(D[2 * nt2], a[kc], b);
            mma16816(D[2 * nt2 + 1], a[kc], b + 2);
        }
}

// pack D (8 ntiles) -> next-GEMM A fragments
__device__ __forceinline__ void pack_a(const float D[8][4], unsigned a[4][4]) {
#pragma unroll
    for (int kc = 0; kc < 4; kc++) {
        a[kc][0] = packh2(D[2 * kc][0], D[2 * kc][1]);
        a[kc][1] = packh2(D[2 * kc][2], D[2 * kc][3]);
        a[kc][2] = packh2(D[2 * kc + 1][0], D[2 * kc + 1][1]);
        a[kc][3] = packh2(D[2 * kc + 1][2], D[2 * kc + 1][3]);
    }
}

// ---------------- filter-network lookup table (fp32 values) -------
__global__ void k_tables(const float* __restrict__ fW1, const float* __restrict__ fb1,
                         const float* __restrict__ fW2, const float* __restrict__ fb2) {
    int l = blockIdx.y;
    int i = blockIdx.x;
    int c = threadIdx.x;
    __shared__ float rbf[N_RBF];
    __shared__ float h[HID];

    float w = CUTOFF * (float)i / (float)TABLE;
    if (c < N_RBF) {
        float delta = CUTOFF / (float)(N_RBF - 1);
        float off = delta * (float)c;
        float coeff = -0.5f / (delta * delta);
        float d = w - off;
        rbf[c] = expf(coeff * d * d);
    }
    __syncthreads();

    const float* W1 = fW1 + (l * HID + c) * N_RBF;
    float acc = fb1[l * HID + c];
#pragma unroll
    for (int k = 0; k < N_RBF; k++) acc += rbf[k] * W1[k];
    h[c] = acc / (1.0f + expf(-acc));
    __syncthreads();

    const float* W2 = fW2 + (l * HID + c) * HID;
    float acc2 = fb2[l * HID + c];
#pragma unroll
    for (int k = 0; k < HID; k++) acc2 += h[k] * W2[k];
    g_tabf[l][i * HID + c] = acc2;
}

__global__ void k_tabpack() {
    int idx = blockIdx.x * blockDim.x + threadIdx.x;
    if (idx >= N_LAYERS * TABLE * 32) return;
    int j = idx & 31;
    int i = (idx >> 5) % TABLE;
    int l = idx / (TABLE * 32);
    float2 v = *(const float2*)&g_tabf[l][i * HID + j * 2];
    float2 vn = *(const float2*)&g_tabf[l][(i + 1) * HID + j * 2];
    uint2 o;
    o.x = packh2(v.x, v.y);
    o.y = packh2(vn.x - v.x, vn.y - v.y);
    *(uint2*)&g_tabh[l][i * 128 + j * 4] = o;
}

// ---------------- per-launch zeroing ------------------------------
__global__ void k_zero() {
    int idx = blockIdx.x * blockDim.x + threadIdx.x;
    if (idx < N_NODES) g_hist[idx] = 0;
    if (idx < N_GRAPHS * HID) g_pooled[idx] = 0.0f;
    if (idx < N_GRAPHS) g_counts[idx] = 0.0f;
}

// ---------------- CSR build ---------------------------------------
__global__ void k_hist(const int* __restrict__ edge_index) {
    int e = blockIdx.x * blockDim.x + threadIdx.x;
    if (e >= N_EDGES) return;
    atomicAdd(&g_hist[edge_index[N_EDGES + e]], 1);
}

__global__ void k_scan_a() {
    __shared__ int ws[8];
    int b = blockIdx.x, t = threadIdx.x;
    int base = b * SCAN_BLK + t * 4;
    int s = 0;
#pragma unroll
    for (int i = 0; i < 4; i++) {
        int idx = base + i;
        if (idx < N_NODES) s += g_hist[idx];
    }
#pragma unroll
    for (int o = 16; o; o >>= 1) s += __shfl_down_sync(~0u, s, o);
    if ((t & 31) == 0) ws[t >> 5] = s;
    __syncthreads();
    if (t == 0) {
        int v = 0;
        for (int i = 0; i < 8; i++) v += ws[i];
        g_bsum[b] = v;
    }
}

__global__ void k_scan_b() {
    __shared__ int sm[SCAN_NB];
    int t = threadIdx.x;
    if (t < SCAN_NB) sm[t] = g_bsum[t];
    __syncthreads();
    if (t == 0) {
        int run = 0;
        for (int i = 0; i < SCAN_NB; i++) {
            int v = sm[i];
            sm[i] = run;
            run += v;
        }
    }
    __syncthreads();
    if (t < SCAN_NB) g_bsum[t] = sm[t];
}

__global__ void k_scan_c() {
    __shared__ int wsum[8];
    int b = blockIdx.x, t = threadIdx.x, lane = t & 31, wid = t >> 5;
    int base = b * SCAN_BLK + t * 4;
    int v[4];
    int s = 0;
#pragma unroll
    for (int i = 0; i < 4; i++) {
        int idx = base + i;
        v[i] = (idx < N_NODES) ? g_hist[idx] : 0;
        s += v[i];
    }
    int sc = s;
#pragma unroll
    for (int o = 1; o < 32; o <<= 1) {
        int u = __shfl_up_sync(~0u, sc, o);
        if (lane >= o) sc += u;
    }
    if (lane == 31) wsum[wid] = sc;
    __syncthreads();
    if (t == 0) {
        int run = 0;
        for (int i = 0; i < 8; i++) {
            int u = wsum[i];
            wsum[i] = run;
            run += u;
        }
    }
    __syncthreads();
    int off = g_bsum[b] + wsum[wid] + sc - s;
#pragma unroll
    for (int i = 0; i < 4; i++) {
        int idx = base + i;
        if (idx < N_NODES) {
            g_rowptr[idx] = off;
            g_cursor[idx] = off;
            off += v[i];
        }
    }
    if (b == 0 && t == 0) g_rowptr[N_NODES] = N_EDGES;
}

__global__ void k_scatter(const int* __restrict__ edge_index, const float* __restrict__ ew) {
    int e = blockIdx.x * blockDim.x + threadIdx.x;
    if (e >= N_EDGES) return;
    int src = edge_index[e];
    int dst = edge_index[N_EDGES + e];
    float w = __ldg(&ew[e]);
    float tt = w * ((float)TABLE / CUTOFF);
    int i0 = (int)tt;
    if (i0 < 0) i0 = 0;
    if (i0 > TABLE - 1) i0 = TABLE - 1;
    float fr = tt - (float)i0;
    int pos = atomicAdd(&g_cursor[dst], 1);
    g_col[pos] = make_uint2((unsigned)src | ((unsigned)i0 << 17), __float_as_uint(fr));
}

// ---------------- layer 0: x = emb[z]; y = x @ dW[0].T + db[0] ----
__global__ __launch_bounds__(128) void k_embed_ylinear(const int* __restrict__ z,
                                                       const float* __restrict__ emb,
                                                       const float* __restrict__ dW0,
                                                       const float* __restrict__ db0) {
    __shared__ __align__(16) __half Ah[64][PH];
    __shared__ __align__(16) __half Wh[64][PH];
    int tid = threadIdx.x;
    int node0 = blockIdx.x * 64;
    stage_w(dW0, Wh, tid);
#pragma unroll
    for (int it = 0; it < 8; it++) {
        int idx = it * 128 + tid;
        int q = idx & 15;
        int n = idx >> 4;
        uint2 o = make_uint2(0u, 0u);
        if (node0 + n < N_NODES) {
            int zz = __ldg(&z[node0 + n]);
            float4 v = *(const float4*)&emb[zz * HID + q * 4];
            *(float4*)&g_x[(size_t)(node0 + n) * HID + q * 4] = v;
            o = make_uint2(packh2(v.x, v.y), packh2(v.z, v.w));
        }
        *(uint2*)&Ah[n][q * 4] = o;
    }
    __syncthreads();

    int w = tid >> 5, lane = tid & 31;
    float D[8][4];
    warp_gemm_smemA(Ah, Wh, w, lane, D);

    int qr = lane >> 2, qc = (lane & 3) * 2;
    int row0 = node0 + w * 16 + qr, row1 = row0 + 8;
#pragma unroll
    for (int nt = 0; nt < 8; nt++) {
        int c0 = nt * 8 + qc;
        float bx = __ldg(&db0[c0]), by = __ldg(&db0[c0 + 1]);
        if (row0 < N_NODES)
            *(__half2*)&g_yh[(size_t)row0 * HID + c0] = __floats2half2_rn(D[nt][0] + bx, D[nt][1] + by);
        if (row1 < N_NODES)
            *(__half2*)&g_yh[(size_t)row1 * HID + c0] = __floats2half2_rn(D[nt][2] + bx, D[nt][3] + by);
    }
}

// ---------------- aggregation: warp per dst node, no atomics ------
// fp32 accumulate, fp16 store (same rounding point as before).
__global__ __launch_bounds__(256) void k_agg(int layer) {
    int node = (blockIdx.x * 256 + threadIdx.x) >> 5;
    int lane = threadIdx.x & 31;
    if (node >= N_NODES) return;
    int beg = g_rowptr[node];
    int end = g_rowptr[node + 1];
    const __half* tab = g_tabh[layer];

    float2 acc = make_float2(0.0f, 0.0f);
    uint2 r0, r1;
    if (beg < end) r0 = __ldg(&g_col[beg]);
    if (beg + 1 < end) r1 = __ldg(&g_col[beg + 1]);

    int p = beg;
    for (; p + 1 < end; p += 2) {
        uint2 c0 = r0, c1 = r1;
        if (p + 2 < end) r0 = __ldg(&g_col[p + 2]);
        if (p + 3 < end) r1 = __ldg(&g_col[p + 3]);

        int s0 = (int)(c0.x & 0x1FFFFu), i00 = (int)(c0.x >> 17);
        int s1 = (int)(c1.x & 0x1FFFFu), i01 = (int)(c1.x >> 17);
        float f0 = __uint_as_float(c0.y);
        float f1 = __uint_as_float(c1.y);

        __half2 yh0 = *(const __half2*)&g_yh[(size_t)s0 * HID + lane * 2];
        uint2 tv0 = __ldg((const uint2*)&tab[(size_t)i00 * 128 + lane * 4]);
        __half2 yh1 = *(const __half2*)&g_yh[(size_t)s1 * HID + lane * 2];
        uint2 tv1 = __ldg((const uint2*)&tab[(size_t)i01 * 128 + lane * 4]);

        float2 y0 = __half22float2(yh0);
        float2 v0 = __half22float2(*(__half2*)&tv0.x);
        float2 d0 = __half22float2(*(__half2*)&tv0.y);
        acc.x = fmaf(y0.x, fmaf(f0, d0.x, v0.x), acc.x);
        acc.y = fmaf(y0.y, fmaf(f0, d0.y, v0.y), acc.y);

        float2 y1 = __half22float2(yh1);
        float2 v1 = __half22float2(*(__half2*)&tv1.x);
        float2 d1 = __half22float2(*(__half2*)&tv1.y);
        acc.x = fmaf(y1.x, fmaf(f1, d1.x, v1.x), acc.x);
        acc.y = fmaf(y1.y, fmaf(f1, d1.y, v1.y), acc.y);
    }
    if (p < end) {
        uint2 c0 = r0;
        int s0 = (int)(c0.x & 0x1FFFFu), i00 = (int)(c0.x >> 17);
        float f0 = __uint_as_float(c0.y);
        __half2 yh0 = *(const __half2*)&g_yh[(size_t)s0 * HID + lane * 2];
        uint2 tv0 = __ldg((const uint2*)&tab[(size_t)i00 * 128 + lane * 4]);
        float2 y0 = __half22float2(yh0);
        float2 v0 = __half22float2(*(__half2*)&tv0.x);
        float2 d0 = __half22float2(*(__half2*)&tv0.y);
        acc.x = fmaf(y0.x, fmaf(f0, d0.x, v0.x), acc.x);
        acc.y = fmaf(y0.y, fmaf(f0, d0.y, v0.y), acc.y);
    }
    *(__half2*)&g_aggh[(size_t)node * HID + lane * 2] = __floats2half2_rn(acc.x, acc.y);
}

// -------- node update: x += silu(agg@uW1.T+b1)@uW2.T+b2; fused next-y
// Weights preloaded up-front; one barrier; A staged from fp16 g_aggh.
template <bool LAST>
__global__ __launch_bounds__(128) void k_update(const float* __restrict__ uW1,
                                                const float* __restrict__ ub1,
                                                const float* __restrict__ uW2,
                                                const float* __restrict__ ub2,
                                                const float* __restrict__ dWn,
                                                const float* __restrict__ dbn, int layer) {
    __shared__ __align__(16) __half Ah[64][PH];
    __shared__ __align__(16) __half W1h[64][PH];
    __shared__ __align__(16) __half W2h[64][PH];
    __shared__ __align__(16) __half Wnh[64][PH];
    int tid = threadIdx.x;
    int node0 = blockIdx.x * 64;

    stage_w(uW1 + layer * HID * HID, W1h, tid);
    stage_w(uW2 + layer * HID * HID, W2h, tid);
    if (!LAST) stage_w(dWn, Wnh, tid);
    stage_ah(g_aggh, node0, Ah, tid);
    __syncthreads();   // the ONLY barrier

    int w = tid >> 5, lane = tid & 31;
    int qr = lane >> 2, qc = (lane & 3) * 2;
    int row0 = node0 + w * 16 + qr, row1 = row0 + 8;

    float D[8][4];
    warp_gemm_smemA(Ah, W1h, w, lane, D);

#pragma unroll
    for (int nt = 0; nt < 8; nt++) {
        int c0 = nt * 8 + qc;
        float bx = __ldg(&ub1[layer * HID + c0]), by = __ldg(&ub1[layer * HID + c0 + 1]);
        D[nt][0] = silu_f(D[nt][0] + bx);
        D[nt][1] = silu_f(D[nt][1] + by);
        D[nt][2] = silu_f(D[nt][2] + bx);
        D[nt][3] = silu_f(D[nt][3] + by);
    }
    unsigned a[4][4];
    pack_a(D, a);

    warp_gemm_regA(a, W2h, lane, D);

#pragma unroll
    for (int nt = 0; nt < 8; nt++) {
        int c0 = nt * 8 + qc;
        float bx = __ldg(&ub2[layer * HID + c0]), by = __ldg(&ub2[layer * HID + c0 + 1]);
        if (row0 < N_NODES) {
            float2 xv = *(const float2*)&g_x[(size_t)row0 * HID + c0];
            D[nt][0] += bx + xv.x;
            D[nt][1] += by + xv.y;
            *(float2*)&g_x[(size_t)row0 * HID + c0] = make_float2(D[nt][0], D[nt][1]);
        }
        if (row1 < N_NODES) {
            float2 xv = *(const float2*)&g_x[(size_t)row1 * HID + c0];
            D[nt][2] += bx + xv.x;
            D[nt][3] += by + xv.y;
            *(float2*)&g_x[(size_t)row1 * HID + c0] = make_float2(D[nt][2], D[nt][3]);
        }
    }

    if (!LAST) {
        pack_a(D, a);
        warp_gemm_regA(a, Wnh, lane, D);
#pragma unroll
        for (int nt = 0; nt < 8; nt++) {
            int c0 = nt * 8 + qc;
            float bx = __ldg(&dbn[c0]), by = __ldg(&dbn[c0 + 1]);
            if (row0 < N_NODES)
                *(__half2*)&g_yh[(size_t)row0 * HID + c0] =
                    __floats2half2_rn(D[nt][0] + bx, D[nt][1] + by);
            if (row1 < N_NODES)
                *(__half2*)&g_yh[(size_t)row1 * HID + c0] =
                    __floats2half2_rn(D[nt][2] + bx, D[nt][3] + by);
        }
    }
}

// ---------------- mean pool (batch sorted: segmented flush) -------
__global__ void k_pool(const int* __restrict__ batch) {
    int tid = threadIdx.x;
    int c = tid & 63;
    int grp = tid >> 6;
    long base = (long)blockIdx.x * 64 + grp * 16;
    if (base >= N_NODES) return;

    float acc = 0.0f;
    int cur = -1;
    for (int i = 0; i < 16; i++) {
        long n = base + i;
        if (n >= N_NODES) break;
        int g = __ldg(&batch[n]);
        if (g != cur) {
            if (cur >= 0) atomicAdd(&g_pooled[cur * HID + c], acc);
            cur = g;
            acc = 0.0f;
        }
        acc += g_x[n * HID + c];
    }
    if (cur >= 0) atomicAdd(&g_pooled[cur * HID + c], acc);

    if (c == 0) {
        float cnt = 0.0f;
        int cg2 = -1;
        for (int i = 0; i < 16; i++) {
            long n = base + i;
            if (n >= N_NODES) break;
            int g = __ldg(&batch[n]);
            if (g != cg2) {
                if (cg2 >= 0) atomicAdd(&g_counts[cg2], cnt);
                cg2 = g;
                cnt = 0.0f;
            }
            cnt += 1.0f;
        }
        if (cg2 >= 0) atomicAdd(&g_counts[cg2], cnt);
    }
}

// ---------------- gate MLP + softmax + prediction -----------------
__global__ void k_gate(const float* __restrict__ mlip,
                       const float* __restrict__ gW1, const float* __restrict__ gb1,
                       const float* __restrict__ gW2, const float* __restrict__ gb2,
                       const float* __restrict__ gW3, const float* __restrict__ gb3,
                       float* __restrict__ out) {
    int g = blockIdx.x;
    int c = threadIdx.x;
    __shared__ float in[GATE_IN];
    __shared__ float h1[G1];
    __shared__ float h2[G2];
    __shared__ float lg[N_EXPERTS];

    float cnt = fmaxf(g_counts[g], 1.0f);
    in[c] = g_pooled[g * HID + c] / cnt;
    if (c < N_EXPERTS) in[HID + c] = mlip[g * N_EXPERTS + c];
    __syncthreads();

    float acc = gb1[c];
#pragma unroll
    for (int k = 0; k < GATE_IN; k++) acc += in[k] * gW1[c * GATE_IN + k];
    h1[c] = fmaxf(acc, 0.0f);
    __syncthreads();

    if (c < G2) {
        float a2 = gb2[c];
#pragma unroll
        for (int k = 0; k < G1; k++) a2 += h1[k] * gW2[c * G1 + k];
        h2[c] = fmaxf(a2, 0.0f);
    }
    __syncthreads();

    if (c < N_EXPERTS) {
        float a3 = gb3[c];
#pragma unroll
        for (int k = 0; k < G2; k++) a3 += h2[k] * gW3[c * G2 + k];
        lg[c] = a3;
        out[g * N_EXPERTS + c] = a3;
    }
    __syncthreads();

    if (c == 0) {
        float m = lg[0];
        for (int k = 1; k < N_EXPERTS; k++) m = fmaxf(m, lg[k]);
        float wts[N_EXPERTS];
        float ssum = 0.0f;
        for (int k = 0; k < N_EXPERTS; k++) {
            wts[k] = expf(lg[k] - m);
            ssum += wts[k];
        }
        float pred = 0.0f;
        for (int k = 0; k < N_EXPERTS; k++) {
            float wv = wts[k] / ssum;
            out[N_GRAPHS * N_EXPERTS + g * N_EXPERTS + k] = wv;
            pred += mlip[g * N_EXPERTS + k] * wv;
        }
        out[2 * N_GRAPHS * N_EXPERTS + g] = pred;
    }
}

// ---------------- launch ------------------------------------------
extern "C" void kernel_launch(void* const* d_in, const int* in_sizes, int n_in,
                              void* d_out, int out_size) {
    const int* z = (const int*)d_in[0];
    const int* edge_index = (const int*)d_in[1];
    const float* ew = (const float*)d_in[2];
    const int* batch = (const int*)d_in[3];
    const float* mlip = (const float*)d_in[4];
    const float* emb = (const float*)d_in[5];
    const float* fW1 = (const float*)d_in[6];
    const float* fb1 = (const float*)d_in[7];
    const float* fW2 = (const float*)d_in[8];
    const float* fb2 = (const float*)d_in[9];
    const float* dW = (const float*)d_in[10];
    const float* db = (const float*)d_in[11];
    const float* uW1 = (const float*)d_in[12];
    const float* ub1 = (const float*)d_in[13];
    const float* uW2 = (const float*)d_in[14];
    const float* ub2 = (const float*)d_in[15];
    const float* gW1 = (const float*)d_in[16];
    const float* gb1 = (const float*)d_in[17];
    const float* gW2 = (const float*)d_in[18];
    const float* gb2 = (const float*)d_in[19];
    const float* gW3 = (const float*)d_in[20];
    const float* gb3 = (const float*)d_in[21];
    float* out = (float*)d_out;

    k_zero<<<(N_NODES + 255) / 256, 256>>>();
    k_hist<<<(N_EDGES + 255) / 256, 256>>>(edge_index);
    k_scan_a<<<SCAN_NB, 256>>>();
    k_scan_b<<<1, 128>>>();
    k_scan_c<<<SCAN_NB, 256>>>();
    k_scatter<<<(N_EDGES + 255) / 256, 256>>>(edge_index, ew);
    {
        dim3 grid(TABLE + 1, N_LAYERS);
        k_tables<<<grid, HID>>>(fW1, fb1, fW2, fb2);
        int total = N_LAYERS * TABLE * 32;
        k_tabpack<<<(total + 255) / 256, 256>>>();
    }

    int node_blocks = (N_NODES + 63) / 64;        // 1563
    int agg_blocks = (N_NODES * 32 + 255) / 256;  // 12500

    k_embed_ylinear<<<node_blocks, 128>>>(z, emb, dW, db);

    k_agg<<<agg_blocks, 256>>>(0);
    k_update<false><<<node_blocks, 128>>>(uW1, ub1, uW2, ub2, dW + 1 * HID * HID, db + 1 * HID, 0);
    k_agg<<<agg_blocks, 256>>>(1);
    k_update<false><<<node_blocks, 128>>>(uW1, ub1, uW2, ub2, dW + 2 * HID * HID, db + 2 * HID, 1);
    k_agg<<<agg_blocks, 256>>>(2);
    k_update<true><<<node_blocks, 128>>>(uW1, ub1, uW2, ub2, (const float*)0, (const float*)0, 2);

    k_pool<<<node_blocks, 256>>>(batch);
    k_gate<<<N_GRAPHS, HID>>>(mlip, gW1, gb1, gW2, gb2, gW3, gb3, out);
}

// round 17
// speedup vs baseline: 1.0767x; 1.0147x over previous
#include <cuda_runtime.h>
#include <cuda_fp16.h>
#include <math.h>

#define N_NODES   100000
#define N_EDGES   1250000
#define HID       64
#define N_RBF     32
#define N_GRAPHS  512
#define N_EXPERTS 8
#define N_LAYERS  3
#define MAX_Z     100
#define GATE_IN   72
#define G1        64
#define G2        32
#define TABLE     4096
#define CUTOFF    6.0f
#define PH        72      // smem half pitch (halves)
#define SCAN_BLK  1024
#define SCAN_NB   ((N_NODES + SCAN_BLK - 1) / SCAN_BLK)  // 98

// ---------------- scratch (no allocations allowed) ----------------
__device__ __align__(256) float  g_x[N_NODES * HID];     // retired (layout kept)
__device__ __align__(256) __half g_yh[N_NODES * HID];
__device__ __align__(256) float  g_agg[N_NODES * HID];   // retired (layout kept)
__device__ __align__(256) float  g_tabf[N_LAYERS][(TABLE + 1) * HID];
// packed half table: per row i (256B): 32 x { val half2, delta half2 }
__device__ __align__(256) __half g_tabh[N_LAYERS][TABLE * 128];
__device__ __align__(256) float  g_pooled[N_GRAPHS * HID];
__device__ float g_counts[N_GRAPHS];
// dst-sorted CSR
__device__ __align__(256) int   g_hist[N_NODES];
__device__ __align__(256) int   g_rowptr[N_NODES + 1];
__device__ __align__(256) int   g_cursor[N_NODES];
__device__ __align__(256) uint2 g_col[N_EDGES];   // .x = src | (i0<<17), .y = bits(fr)
__device__ int g_bsum[SCAN_NB];
// appended: fp16 aggregation buffer (halves g_agg traffic)
__device__ __align__(256) __half g_aggh[N_NODES * HID];
// appended: fp16 node-state buffer (halves g_x traffic)
__device__ __align__(256) __half g_xh[N_NODES * HID];

__device__ __forceinline__ float silu_f(float v) { return v / (1.0f + __expf(-v)); }

// ---------------- mma / ldmatrix helpers --------------------------
__device__ __forceinline__ unsigned smem_u32(const void* p) {
    return (unsigned)__cvta_generic_to_shared(p);
}
__device__ __forceinline__ void ldmx4(unsigned addr, unsigned& r0, unsigned& r1,
                                      unsigned& r2, unsigned& r3) {
    asm volatile("ldmatrix.sync.aligned.m8n8.x4.shared.b16 {%0,%1,%2,%3}, [%4];"
                 : "=r"(r0), "=r"(r1), "=r"(r2), "=r"(r3) : "r"(addr));
}
__device__ __forceinline__ void mma16816(float d[4], const unsigned a[4], const unsigned* b) {
    asm volatile(
        "mma.sync.aligned.m16n8k16.row.col.f32.f16.f16.f32 "
        "{%0,%1,%2,%3}, {%4,%5,%6,%7}, {%8,%9}, {%0,%1,%2,%3};"
        : "+f"(d[0]), "+f"(d[1]), "+f"(d[2]), "+f"(d[3])
        : "r"(a[0]), "r"(a[1]), "r"(a[2]), "r"(a[3]), "r"(b[0]), "r"(b[1]));
}
__device__ __forceinline__ unsigned packh2(float a, float b) {
    __half2 h = __floats2half2_rn(a, b);
    return *(unsigned*)&h;
}

// Stage W (torch [out,in] = [c][k], fp32) -> Wh[c][k] fp16. 128 threads.
__device__ __forceinline__ void stage_w(const float* __restrict__ W, __half (*Wh)[PH], int tid) {
#pragma unroll
    for (int it = 0; it < 8; it++) {
        int idx = it * 128 + tid;
        int kq = idx & 15;
        int c = idx >> 4;
        float4 v = *(const float4*)&W[c * HID + kq * 4];
        unsigned h0 = packh2(v.x, v.y), h1 = packh2(v.z, v.w);
        *(uint2*)&Wh[c][kq * 4] = make_uint2(h0, h1);
    }
}

// Stage fp16 node tile -> Ah[n][k] (plain copy; zero-fill invalid rows). 128 threads.
__device__ __forceinline__ void stage_ah(const __half* __restrict__ src, int node0,
                                         __half (*Ah)[PH], int tid) {
#pragma unroll
    for (int it = 0; it < 4; it++) {
        int idx = it * 128 + tid;   // 0..511
        int q = idx & 7;            // 8 halves per chunk
        int n = idx >> 3;           // 0..63
        uint4 o = make_uint4(0u, 0u, 0u, 0u);
        if (node0 + n < N_NODES)
            o = *(const uint4*)&src[(size_t)(node0 + n) * HID + q * 8];
        *(uint4*)&Ah[n][q * 8] = o;
    }
}

// Full 16x64x64 warp GEMM: D = Ah(rows 16w..16w+15) @ Wh^T.
__device__ __forceinline__ void warp_gemm_smemA(const __half (*Ah)[PH], const __half (*Wh)[PH],
                                                int w, int lane, float D[8][4]) {
    int r = lane & 7, m = lane >> 3;
    unsigned a[4][4];
#pragma unroll
    for (int kc = 0; kc < 4; kc++)
        ldmx4(smem_u32(&Ah[w * 16 + r + (m & 1) * 8][kc * 16 + (m >> 1) * 8]),
              a[kc][0], a[kc][1], a[kc][2], a[kc][3]);
#pragma unroll
    for (int i = 0; i < 8; i++)
#pragma unroll
        for (int j = 0; j < 4; j++) D[i][j] = 0.0f;
#pragma unroll
    for (int kc = 0; kc < 4; kc++)
#pragma unroll
        for (int nt2 = 0; nt2 < 4; nt2++) {
            unsigned b[4];
            ldmx4(smem_u32(&Wh[nt2 * 16 + r + (m >> 1) * 8][kc * 16 + (m & 1) * 8]),
                  b[0], b[1], b[2], b[3]);
            mma16816(D[2 * nt2], a[kc], b);
            mma16816(D[2 * nt2 + 1], a[kc], b + 2);
        }
}

// Same, but A fragments already in registers.
__device__ __forceinline__ void warp_gemm_regA(const unsigned a[4][4], const __half (*Wh)[PH],
                                               int lane, float D[8][4]) {
    int r = lane & 7, m = lane >> 3;
#pragma unroll
    for (int i = 0; i < 8; i++)
#pragma unroll
        for (int j = 0; j < 4; j++) D[i][j] = 0.0f;
#pragma unroll
    for (int kc = 0; kc < 4; kc++)
#pragma unroll
        for (int nt2 = 0; nt2 < 4; nt2++) {
            unsigned b[4];
            ldmx4(smem_u32(&Wh[nt2 * 16 + r + (m >> 1) * 8][kc * 16 + (m & 1) * 8]),
                  b[0], b[1], b[2], b[3]);
            mma16816(D[2 * nt2], a[kc], b);
            mma16816(D[2 * nt2 + 1], a[kc], b + 2);
        }
}

// pack D (8 ntiles) -> next-GEMM A fragments
__device__ __forceinline__ void pack_a(const float D[8][4], unsigned a[4][4]) {
#pragma unroll
    for (int kc = 0; kc < 4; kc++) {
        a[kc][0] = packh2(D[2 * kc][0], D[2 * kc][1]);
        a[kc][1] = packh2(D[2 * kc][2], D[2 * kc][3]);
        a[kc][2] = packh2(D[2 * kc + 1][0], D[2 * kc + 1][1]);
        a[kc][3] = packh2(D[2 * kc + 1][2], D[2 * kc + 1][3]);
    }
}

// ---------------- filter-network lookup table (fp32 values) -------
__global__ void k_tables(const float* __restrict__ fW1, const float* __restrict__ fb1,
                         const float* __restrict__ fW2, const float* __restrict__ fb2) {
    int l = blockIdx.y;
    int i = blockIdx.x;
    int c = threadIdx.x;
    __shared__ float rbf[N_RBF];
    __shared__ float h[HID];

    float w = CUTOFF * (float)i / (float)TABLE;
    if (c < N_RBF) {
        float delta = CUTOFF / (float)(N_RBF - 1);
        float off = delta * (float)c;
        float coeff = -0.5f / (delta * delta);
        float d = w - off;
        rbf[c] = expf(coeff * d * d);
    }
    __syncthreads();

    const float* W1 = fW1 + (l * HID + c) * N_RBF;
    float acc = fb1[l * HID + c];
#pragma unroll
    for (int k = 0; k < N_RBF; k++) acc += rbf[k] * W1[k];
    h[c] = acc / (1.0f + expf(-acc));
    __syncthreads();

    const float* W2 = fW2 + (l * HID + c) * HID;
    float acc2 = fb2[l * HID + c];
#pragma unroll
    for (int k = 0; k < HID; k++) acc2 += h[k] * W2[k];
    g_tabf[l][i * HID + c] = acc2;
}

__global__ void k_tabpack() {
    int idx = blockIdx.x * blockDim.x + threadIdx.x;
    if (idx >= N_LAYERS * TABLE * 32) return;
    int j = idx & 31;
    int i = (idx >> 5) % TABLE;
    int l = idx / (TABLE * 32);
    float2 v = *(const float2*)&g_tabf[l][i * HID + j * 2];
    float2 vn = *(const float2*)&g_tabf[l][(i + 1) * HID + j * 2];
    uint2 o;
    o.x = packh2(v.x, v.y);
    o.y = packh2(vn.x - v.x, vn.y - v.y);
    *(uint2*)&g_tabh[l][i * 128 + j * 4] = o;
}

// ---------------- per-launch zeroing ------------------------------
__global__ void k_zero() {
    int idx = blockIdx.x * blockDim.x + threadIdx.x;
    if (idx < N_NODES) g_hist[idx] = 0;
    if (idx < N_GRAPHS * HID) g_pooled[idx] = 0.0f;
    if (idx < N_GRAPHS) g_counts[idx] = 0.0f;
}

// ---------------- CSR build ---------------------------------------
__global__ void k_hist(const int* __restrict__ edge_index) {
    int e = blockIdx.x * blockDim.x + threadIdx.x;
    if (e >= N_EDGES) return;
    atomicAdd(&g_hist[edge_index[N_EDGES + e]], 1);
}

__global__ void k_scan_a() {
    __shared__ int ws[8];
    int b = blockIdx.x, t = threadIdx.x;
    int base = b * SCAN_BLK + t * 4;
    int s = 0;
#pragma unroll
    for (int i = 0; i < 4; i++) {
        int idx = base + i;
        if (idx < N_NODES) s += g_hist[idx];
    }
#pragma unroll
    for (int o = 16; o; o >>= 1) s += __shfl_down_sync(~0u, s, o);
    if ((t & 31) == 0) ws[t >> 5] = s;
    __syncthreads();
    if (t == 0) {
        int v = 0;
        for (int i = 0; i < 8; i++) v += ws[i];
        g_bsum[b] = v;
    }
}

__global__ void k_scan_b() {
    __shared__ int sm[SCAN_NB];
    int t = threadIdx.x;
    if (t < SCAN_NB) sm[t] = g_bsum[t];
    __syncthreads();
    if (t == 0) {
        int run = 0;
        for (int i = 0; i < SCAN_NB; i++) {
            int v = sm[i];
            sm[i] = run;
            run += v;
        }
    }
    __syncthreads();
    if (t < SCAN_NB) g_bsum[t] = sm[t];
}

__global__ void k_scan_c() {
    __shared__ int wsum[8];
    int b = blockIdx.x, t = threadIdx.x, lane = t & 31, wid = t >> 5;
    int base = b * SCAN_BLK + t * 4;
    int v[4];
    int s = 0;
#pragma unroll
    for (int i = 0; i < 4; i++) {
        int idx = base + i;
        v[i] = (idx < N_NODES) ? g_hist[idx] : 0;
        s += v[i];
    }
    int sc = s;
#pragma unroll
    for (int o = 1; o < 32; o <<= 1) {
        int u = __shfl_up_sync(~0u, sc, o);
        if (lane >= o) sc += u;
    }
    if (lane == 31) wsum[wid] = sc;
    __syncthreads();
    if (t == 0) {
        int run = 0;
        for (int i = 0; i < 8; i++) {
            int u = wsum[i];
            wsum[i] = run;
            run += u;
        }
    }
    __syncthreads();
    int off = g_bsum[b] + wsum[wid] + sc - s;
#pragma unroll
    for (int i = 0; i < 4; i++) {
        int idx = base + i;
        if (idx < N_NODES) {
            g_rowptr[idx] = off;
            g_cursor[idx] = off;
            off += v[i];
        }
    }
    if (b == 0 && t == 0) g_rowptr[N_NODES] = N_EDGES;
}

__global__ void k_scatter(const int* __restrict__ edge_index, const float* __restrict__ ew) {
    int e = blockIdx.x * blockDim.x + threadIdx.x;
    if (e >= N_EDGES) return;
    int src = edge_index[e];
    int dst = edge_index[N_EDGES + e];
    float w = __ldg(&ew[e]);
    float tt = w * ((float)TABLE / CUTOFF);
    int i0 = (int)tt;
    if (i0 < 0) i0 = 0;
    if (i0 > TABLE - 1) i0 = TABLE - 1;
    float fr = tt - (float)i0;
    int pos = atomicAdd(&g_cursor[dst], 1);
    g_col[pos] = make_uint2((unsigned)src | ((unsigned)i0 << 17), __float_as_uint(fr));
}

// ---------------- layer 0: x = emb[z]; y = x @ dW[0].T + db[0] ----
__global__ __launch_bounds__(128) void k_embed_ylinear(const int* __restrict__ z,
                                                       const float* __restrict__ emb,
                                                       const float* __restrict__ dW0,
                                                       const float* __restrict__ db0) {
    __shared__ __align__(16) __half Ah[64][PH];
    __shared__ __align__(16) __half Wh[64][PH];
    int tid = threadIdx.x;
    int node0 = blockIdx.x * 64;
    stage_w(dW0, Wh, tid);
#pragma unroll
    for (int it = 0; it < 8; it++) {
        int idx = it * 128 + tid;
        int q = idx & 15;
        int n = idx >> 4;
        uint2 o = make_uint2(0u, 0u);
        if (node0 + n < N_NODES) {
            int zz = __ldg(&z[node0 + n]);
            float4 v = *(const float4*)&emb[zz * HID + q * 4];
            o = make_uint2(packh2(v.x, v.y), packh2(v.z, v.w));
            *(uint2*)&g_xh[(size_t)(node0 + n) * HID + q * 4] = o;  // fp16 node state
        }
        *(uint2*)&Ah[n][q * 4] = o;
    }
    __syncthreads();

    int w = tid >> 5, lane = tid & 31;
    float D[8][4];
    warp_gemm_smemA(Ah, Wh, w, lane, D);

    int qr = lane >> 2, qc = (lane & 3) * 2;
    int row0 = node0 + w * 16 + qr, row1 = row0 + 8;
#pragma unroll
    for (int nt = 0; nt < 8; nt++) {
        int c0 = nt * 8 + qc;
        float bx = __ldg(&db0[c0]), by = __ldg(&db0[c0 + 1]);
        if (row0 < N_NODES)
            *(__half2*)&g_yh[(size_t)row0 * HID + c0] = __floats2half2_rn(D[nt][0] + bx, D[nt][1] + by);
        if (row1 < N_NODES)
            *(__half2*)&g_yh[(size_t)row1 * HID + c0] = __floats2half2_rn(D[nt][2] + bx, D[nt][3] + by);
    }
}

// ---------------- aggregation: warp per dst node, no atomics ------
// fp32 accumulate, fp16 store.
__global__ __launch_bounds__(256) void k_agg(int layer) {
    int node = (blockIdx.x * 256 + threadIdx.x) >> 5;
    int lane = threadIdx.x & 31;
    if (node >= N_NODES) return;
    int beg = g_rowptr[node];
    int end = g_rowptr[node + 1];
    const __half* tab = g_tabh[layer];

    float2 acc = make_float2(0.0f, 0.0f);
    uint2 r0, r1;
    if (beg < end) r0 = __ldg(&g_col[beg]);
    if (beg + 1 < end) r1 = __ldg(&g_col[beg + 1]);

    int p = beg;
    for (; p + 1 < end; p += 2) {
        uint2 c0 = r0, c1 = r1;
        if (p + 2 < end) r0 = __ldg(&g_col[p + 2]);
        if (p + 3 < end) r1 = __ldg(&g_col[p + 3]);

        int s0 = (int)(c0.x & 0x1FFFFu), i00 = (int)(c0.x >> 17);
        int s1 = (int)(c1.x & 0x1FFFFu), i01 = (int)(c1.x >> 17);
        float f0 = __uint_as_float(c0.y);
        float f1 = __uint_as_float(c1.y);

        __half2 yh0 = *(const __half2*)&g_yh[(size_t)s0 * HID + lane * 2];
        uint2 tv0 = __ldg((const uint2*)&tab[(size_t)i00 * 128 + lane * 4]);
        __half2 yh1 = *(const __half2*)&g_yh[(size_t)s1 * HID + lane * 2];
        uint2 tv1 = __ldg((const uint2*)&tab[(size_t)i01 * 128 + lane * 4]);

        float2 y0 = __half22float2(yh0);
        float2 v0 = __half22float2(*(__half2*)&tv0.x);
        float2 d0 = __half22float2(*(__half2*)&tv0.y);
        acc.x = fmaf(y0.x, fmaf(f0, d0.x, v0.x), acc.x);
        acc.y = fmaf(y0.y, fmaf(f0, d0.y, v0.y), acc.y);

        float2 y1 = __half22float2(yh1);
        float2 v1 = __half22float2(*(__half2*)&tv1.x);
        float2 d1 = __half22float2(*(__half2*)&tv1.y);
        acc.x = fmaf(y1.x, fmaf(f1, d1.x, v1.x), acc.x);
        acc.y = fmaf(y1.y, fmaf(f1, d1.y, v1.y), acc.y);
    }
    if (p < end) {
        uint2 c0 = r0;
        int s0 = (int)(c0.x & 0x1FFFFu), i00 = (int)(c0.x >> 17);
        float f0 = __uint_as_float(c0.y);
        __half2 yh0 = *(const __half2*)&g_yh[(size_t)s0 * HID + lane * 2];
        uint2 tv0 = __ldg((const uint2*)&tab[(size_t)i00 * 128 + lane * 4]);
        float2 y0 = __half22float2(yh0);
        float2 v0 = __half22float2(*(__half2*)&tv0.x);
        float2 d0 = __half22float2(*(__half2*)&tv0.y);
        acc.x = fmaf(y0.x, fmaf(f0, d0.x, v0.x), acc.x);
        acc.y = fmaf(y0.y, fmaf(f0, d0.y, v0.y), acc.y);
    }
    *(__half2*)&g_aggh[(size_t)node * HID + lane * 2] = __floats2half2_rn(acc.x, acc.y);
}

// -------- node update: x += silu(agg@uW1.T+b1)@uW2.T+b2; fused next-y
// Weights preloaded; one barrier; A from fp16 g_aggh; x state in fp16 g_xh.
template <bool LAST>
__global__ __launch_bounds__(128) void k_update(const float* __restrict__ uW1,
                                                const float* __restrict__ ub1,
                                                const float* __restrict__ uW2,
                                                const float* __restrict__ ub2,
                                                const float* __restrict__ dWn,
                                                const float* __restrict__ dbn, int layer) {
    __shared__ __align__(16) __half Ah[64][PH];
    __shared__ __align__(16) __half W1h[64][PH];
    __shared__ __align__(16) __half W2h[64][PH];
    __shared__ __align__(16) __half Wnh[64][PH];
    int tid = threadIdx.x;
    int node0 = blockIdx.x * 64;

    stage_w(uW1 + layer * HID * HID, W1h, tid);
    stage_w(uW2 + layer * HID * HID, W2h, tid);
    if (!LAST) stage_w(dWn, Wnh, tid);
    stage_ah(g_aggh, node0, Ah, tid);
    __syncthreads();   // the ONLY barrier

    int w = tid >> 5, lane = tid & 31;
    int qr = lane >> 2, qc = (lane & 3) * 2;
    int row0 = node0 + w * 16 + qr, row1 = row0 + 8;

    float D[8][4];
    warp_gemm_smemA(Ah, W1h, w, lane, D);

#pragma unroll
    for (int nt = 0; nt < 8; nt++) {
        int c0 = nt * 8 + qc;
        float bx = __ldg(&ub1[layer * HID + c0]), by = __ldg(&ub1[layer * HID + c0 + 1]);
        D[nt][0] = silu_f(D[nt][0] + bx);
        D[nt][1] = silu_f(D[nt][1] + by);
        D[nt][2] = silu_f(D[nt][2] + bx);
        D[nt][3] = silu_f(D[nt][3] + by);
    }
    unsigned a[4][4];
    pack_a(D, a);

    warp_gemm_regA(a, W2h, lane, D);

#pragma unroll
    for (int nt = 0; nt < 8; nt++) {
        int c0 = nt * 8 + qc;
        float bx = __ldg(&ub2[layer * HID + c0]), by = __ldg(&ub2[layer * HID + c0 + 1]);
        if (row0 < N_NODES) {
            float2 xv = __half22float2(*(const __half2*)&g_xh[(size_t)row0 * HID + c0]);
            D[nt][0] += bx + xv.x;
            D[nt][1] += by + xv.y;
            *(__half2*)&g_xh[(size_t)row0 * HID + c0] = __floats2half2_rn(D[nt][0], D[nt][1]);
        }
        if (row1 < N_NODES) {
            float2 xv = __half22float2(*(const __half2*)&g_xh[(size_t)row1 * HID + c0]);
            D[nt][2] += bx + xv.x;
            D[nt][3] += by + xv.y;
            *(__half2*)&g_xh[(size_t)row1 * HID + c0] = __floats2half2_rn(D[nt][2], D[nt][3]);
        }
    }

    if (!LAST) {
        pack_a(D, a);
        warp_gemm_regA(a, Wnh, lane, D);
#pragma unroll
        for (int nt = 0; nt < 8; nt++) {
            int c0 = nt * 8 + qc;
            float bx = __ldg(&dbn[c0]), by = __ldg(&dbn[c0 + 1]);
            if (row0 < N_NODES)
                *(__half2*)&g_yh[(size_t)row0 * HID + c0] =
                    __floats2half2_rn(D[nt][0] + bx, D[nt][1] + by);
            if (row1 < N_NODES)
                *(__half2*)&g_yh[(size_t)row1 * HID + c0] =
                    __floats2half2_rn(D[nt][2] + bx, D[nt][3] + by);
        }
    }
}

// ---------------- mean pool (batch sorted: segmented flush) -------
__global__ void k_pool(const int* __restrict__ batch) {
    int tid = threadIdx.x;
    int c = tid & 63;
    int grp = tid >> 6;
    long base = (long)blockIdx.x * 64 + grp * 16;
    if (base >= N_NODES) return;

    float acc = 0.0f;
    int cur = -1;
    for (int i = 0; i < 16; i++) {
        long n = base + i;
        if (n >= N_NODES) break;
        int g = __ldg(&batch[n]);
        if (g != cur) {
            if (cur >= 0) atomicAdd(&g_pooled[cur * HID + c], acc);
            cur = g;
            acc = 0.0f;
        }
        acc += __half2float(g_xh[n * HID + c]);
    }
    if (cur >= 0) atomicAdd(&g_pooled[cur * HID + c], acc);

    if (c == 0) {
        float cnt = 0.0f;
        int cg2 = -1;
        for (int i = 0; i < 16; i++) {
            long n = base + i;
            if (n >= N_NODES) break;
            int g = __ldg(&batch[n]);
            if (g != cg2) {
                if (cg2 >= 0) atomicAdd(&g_counts[cg2], cnt);
                cg2 = g;
                cnt = 0.0f;
            }
            cnt += 1.0f;
        }
        if (cg2 >= 0) atomicAdd(&g_counts[cg2], cnt);
    }
}

// ---------------- gate MLP + softmax + prediction -----------------
__global__ void k_gate(const float* __restrict__ mlip,
                       const float* __restrict__ gW1, const float* __restrict__ gb1,
                       const float* __restrict__ gW2, const float* __restrict__ gb2,
                       const float* __restrict__ gW3, const float* __restrict__ gb3,
                       float* __restrict__ out) {
    int g = blockIdx.x;
    int c = threadIdx.x;
    __shared__ float in[GATE_IN];
    __shared__ float h1[G1];
    __shared__ float h2[G2];
    __shared__ float lg[N_EXPERTS];

    float cnt = fmaxf(g_counts[g], 1.0f);
    in[c] = g_pooled[g * HID + c] / cnt;
    if (c < N_EXPERTS) in[HID + c] = mlip[g * N_EXPERTS + c];
    __syncthreads();

    float acc = gb1[c];
#pragma unroll
    for (int k = 0; k < GATE_IN; k++) acc += in[k] * gW1[c * GATE_IN + k];
    h1[c] = fmaxf(acc, 0.0f);
    __syncthreads();

    if (c < G2) {
        float a2 = gb2[c];
#pragma unroll
        for (int k = 0; k < G1; k++) a2 += h1[k] * gW2[c * G1 + k];
        h2[c] = fmaxf(a2, 0.0f);
    }
    __syncthreads();

    if (c < N_EXPERTS) {
        float a3 = gb3[c];
#pragma unroll
        for (int k = 0; k < G2; k++) a3 += h2[k] * gW3[c * G2 + k];
        lg[c] = a3;
        out[g * N_EXPERTS + c] = a3;
    }
    __syncthreads();

    if (c == 0) {
        float m = lg[0];
        for (int k = 1; k < N_EXPERTS; k++) m = fmaxf(m, lg[k]);
        float wts[N_EXPERTS];
        float ssum = 0.0f;
        for (int k = 0; k < N_EXPERTS; k++) {
            wts[k] = expf(lg[k] - m);
            ssum += wts[k];
        }
        float pred = 0.0f;
        for (int k = 0; k < N_EXPERTS; k++) {
            float wv = wts[k] / ssum;
            out[N_GRAPHS * N_EXPERTS + g * N_EXPERTS + k] = wv;
            pred += mlip[g * N_EXPERTS + k] * wv;
        }
        out[2 * N_GRAPHS * N_EXPERTS + g] = pred;
    }
}

// ---------------- launch ------------------------------------------
extern "C" void kernel_launch(void* const* d_in, const int* in_sizes, int n_in,
                              void* d_out, int out_size) {
    const int* z = (const int*)d_in[0];
    const int* edge_index = (const int*)d_in[1];
    const float* ew = (const float*)d_in[2];
    const int* batch = (const int*)d_in[3];
    const float* mlip = (const float*)d_in[4];
    const float* emb = (const float*)d_in[5];
    const float* fW1 = (const float*)d_in[6];
    const float* fb1 = (const float*)d_in[7];
    const float* fW2 = (const float*)d_in[8];
    const float* fb2 = (const float*)d_in[9];
    const float* dW = (const float*)d_in[10];
    const float* db = (const float*)d_in[11];
    const float* uW1 = (const float*)d_in[12];
    const float* ub1 = (const float*)d_in[13];
    const float* uW2 = (const float*)d_in[14];
    const float* ub2 = (const float*)d_in[15];
    const float* gW1 = (const float*)d_in[16];
    const float* gb1 = (const float*)d_in[17];
    const float* gW2 = (const float*)d_in[18];
    const float* gb2 = (const float*)d_in[19];
    const float* gW3 = (const float*)d_in[20];
    const float* gb3 = (const float*)d_in[21];
    float* out = (float*)d_out;

    k_zero<<<(N_NODES + 255) / 256, 256>>>();
    k_hist<<<(N_EDGES + 255) / 256, 256>>>(edge_index);
    k_scan_a<<<SCAN_NB, 256>>>();
    k_scan_b<<<1, 128>>>();
    k_scan_c<<<SCAN_NB, 256>>>();
    k_scatter<<<(N_EDGES + 255) / 256, 256>>>(edge_index, ew);
    {
        dim3 grid(TABLE + 1, N_LAYERS);
        k_tables<<<grid, HID>>>(fW1, fb1, fW2, fb2);
        int total = N_LAYERS * TABLE * 32;
        k_tabpack<<<(total + 255) / 256, 256>>>();
    }

    int node_blocks = (N_NODES + 63) / 64;        // 1563
    int agg_blocks = (N_NODES * 32 + 255) / 256;  // 12500

    k_embed_ylinear<<<node_blocks, 128>>>(z, emb, dW, db);

    k_agg<<<agg_blocks, 256>>>(0);
    k_update<false><<<node_blocks, 128>>>(uW1, ub1, uW2, ub2, dW + 1 * HID * HID, db + 1 * HID, 0);
    k_agg<<<agg_blocks, 256>>>(1);
    k_update<false><<<node_blocks, 128>>>(uW1, ub1, uW2, ub2, dW + 2 * HID * HID, db + 2 * HID, 1);
    k_agg<<<agg_blocks, 256>>>(2);
    k_update<true><<<node_blocks, 128>>>(uW1, ub1, uW2, ub2, (const float*)0, (const float*)0, 2);

    k_pool<<<node_blocks, 256>>>(batch);
    k_gate<<<N_GRAPHS, HID>>>(mlip, gW1, gb1, gW2, gb2, gW3, gb3, out);
}